// round 10
// baseline (speedup 1.0000x reference)
#include <cuda_runtime.h>
#include <cuda_bf16.h>

#define SEQ   4096
#define DIM   512
#define DIM1  513
#define PI_F  3.14159265358979f

// Output-vectorized concat, ILP=8: each thread produces 8 aligned float4s of
// the flat [B*S*513] output, spaced blockDim apart so every LDG/STG stays
// warp-coalesced. 32 independent streaming loads per thread -> deep MLP.
// __ldcs/__stcs: zero-reuse stream, evict-first to keep L2 out of the way.
//
// Index identity per group (base=i4*4, r=base/513, c=base-513r):
//   output elem j in [0,4):  pe-channel iff j == 512-c
//   input addr             :  r*512 + c + j - (c+j >= 513)
__global__ __launch_bounds__(256) void pe_concat_kernel(
    const float* __restrict__ in,
    const int*   __restrict__ lengths,
    float*       __restrict__ out)
{
    const int i4_0 = blockIdx.x * (256 * 8) + threadIdx.x;

    float4 o[8];
#pragma unroll
    for (int g = 0; g < 8; g++) {
        const int i4   = i4_0 + g * 256;
        const int base = i4 * 4;
        const int r    = base / DIM1;            // const-div -> mulhi
        const int c    = base - r * DIM1;
        const int kpe  = DIM - c;                // j-index of pe elem (may be >=4)
        const float* p = in + r * DIM + c;

        float v[4];
#pragma unroll
        for (int j = 0; j < 4; j++) {
            const int adj = (j > kpe) ? 1 : 0;   // skip over pe column
            v[j] = (j == kpe) ? 0.0f : __ldcs(p + j - adj);
        }

        if (kpe < 4) {                           // ~0.78% of groups
            const int b = r >> 12;               // row / 4096
            const int s = r & (SEQ - 1);         // row % 4096
            const float fl   = (float)__ldg(lengths + b);
            const float safe = fmaxf(fl, 1.0f);
            v[kpe] = ((float)s < fl) ? __cosf(((float)s / safe) * PI_F) : 0.0f;
        }

        o[g].x = v[0]; o[g].y = v[1]; o[g].z = v[2]; o[g].w = v[3];
    }

    float4* out4 = reinterpret_cast<float4*>(out);
#pragma unroll
    for (int g = 0; g < 8; g++)
        __stcs(out4 + i4_0 + g * 256, o[g]);
}

extern "C" void kernel_launch(void* const* d_in, const int* in_sizes, int n_in,
                              void* d_out, int out_size)
{
    const float* in      = (const float*)d_in[0];   // [16, 4096, 512] f32
    const int*   lengths = (const int*)  d_in[1];   // [16] i32
    float*       out     = (float*)d_out;           // [16, 4096, 513] f32

    // out_size = 16*4096*513 = 33,619,968 floats = 8,404,992 float4
    //          = 4104 blocks * (256 threads * 8 float4), exact
    (void)in_sizes; (void)n_in; (void)out_size;
    pe_concat_kernel<<<4104, 256>>>(in, lengths, out);
}

// round 11
// speedup vs baseline: 1.1217x; 1.1217x over previous
#include <cuda_runtime.h>
#include <cuda_bf16.h>

#define SEQ   4096
#define DIM   512
#define DIM1  513
#define PI_F  3.14159265358979f

// Output-vectorized concat, ILP=4 (the measured sweet spot: regs~31, occ~72%).
// Each thread produces 4 aligned float4s of the flat [B*S*513] output, spaced
// blockDim apart so every LDG/STG stays warp-coalesced; 16 independent loads
// per thread. .cs (evict-first) on both streams: zero reuse, keep L2 clear
// for write-back drain.
//
// Index identity per group (base=i4*4, r=base/513, c=base-513r):
//   output elem j in [0,4):  pe-channel iff j == 512-c
//   input addr             :  r*512 + c + j - (c+j >= 513)
// (a window never spans more than one row boundary since 513 > 4)
__global__ __launch_bounds__(256) void pe_concat_kernel(
    const float* __restrict__ in,
    const int*   __restrict__ lengths,
    float*       __restrict__ out)
{
    const int i4_0 = blockIdx.x * 1024 + threadIdx.x;

    float4 o[4];
#pragma unroll
    for (int g = 0; g < 4; g++) {
        const int i4   = i4_0 + g * 256;
        const int base = i4 * 4;
        const int r    = base / DIM1;            // const-div -> mulhi
        const int c    = base - r * DIM1;
        const int kpe  = DIM - c;                // j-index of pe elem (may be >=4)
        const float* p = in + r * DIM + c;

        float v[4];
#pragma unroll
        for (int j = 0; j < 4; j++) {
            const int adj = (j > kpe) ? 1 : 0;   // skip over pe column
            v[j] = (j == kpe) ? 0.0f : __ldcs(p + j - adj);
        }

        if (kpe < 4) {                           // ~0.78% of groups
            const int b = r >> 12;               // row / 4096
            const int s = r & (SEQ - 1);         // row % 4096
            const float fl   = (float)__ldg(lengths + b);
            const float safe = fmaxf(fl, 1.0f);
            v[kpe] = ((float)s < fl) ? __cosf(((float)s / safe) * PI_F) : 0.0f;
        }

        o[g].x = v[0]; o[g].y = v[1]; o[g].z = v[2]; o[g].w = v[3];
    }

    float4* out4 = reinterpret_cast<float4*>(out);
#pragma unroll
    for (int g = 0; g < 4; g++)
        __stcs(out4 + i4_0 + g * 256, o[g]);
}

extern "C" void kernel_launch(void* const* d_in, const int* in_sizes, int n_in,
                              void* d_out, int out_size)
{
    const float* in      = (const float*)d_in[0];   // [16, 4096, 512] f32
    const int*   lengths = (const int*)  d_in[1];   // [16] i32
    float*       out     = (float*)d_out;           // [16, 4096, 513] f32

    // out_size = 16*4096*513 = 33,619,968 floats = 8,404,992 float4
    //          = 8208 blocks * (256 threads * 4 float4), exact -> no bounds
    (void)in_sizes; (void)n_in; (void)out_size;
    pe_concat_kernel<<<8208, 256>>>(in, lengths, out);
}